// round 6
// baseline (speedup 1.0000x reference)
#include <cuda_runtime.h>
#include <cuda_bf16.h>

// TransientCombNoise: B=32, T=2000, BLOCK=64, MAX_DELAY=480, SR=16000.
// Per row r of N=64000, params (p0..p3):
//   att   = max(16000*(0.0005 + p0*0.0495), 1)   (always >= 8)
//   energy= p1 ; tilt = 2*p2 - 1
//   delay = int(64*(0.5 + 0.5*(0.05 + 0.95*p3)))  in [33, 63]
//   x[i]  = noise[i] * exp(-i/att) * energy
//   y[i]  = x[i] + tilt * x[i-delay]   (single feed-forward tap since delay >= 33)
//   out   = y * rsqrt(mean(y^2) + 1e-5)
//
// y[i] = env(i)*energy*( noise[i] + tilt*exp(delay/att)*noise[i-delay] )
// => tap is a plain global reload (L1 hit, same 256B row).
//
// Instruction-lean: rcp.approx + ex2.approx (log2e folded), 32-bit indexing,
// exact grid (no bounds check). RMS reduction = 4-step shfl.bfly over the
// 16-lane row group (redux.sync.add.f32 is unavailable at compute_103).

#define N_ROWS (32 * 2000)
#define LOG2E 1.4426950408889634f

__global__ __launch_bounds__(256) void tcn_kernel(
    const float4* __restrict__ params,  // [N_ROWS] float4
    const float*  __restrict__ noise,   // [N_ROWS, 64]
    float*        __restrict__ out)     // [N_ROWS, 64]
{
    const int tid  = blockIdx.x * 256 + threadIdx.x;
    const int row  = tid >> 4;          // 16 lanes per row
    const int l    = tid & 15;

    const float4 p = __ldg(params + row);

    // Strict-rounded chain so the truncated delay matches JAX's unfused fp32 math.
    const float att    = fmaxf(__fmul_rn(16000.0f,
                               __fadd_rn(0.0005f, __fmul_rn(p.x, 0.0495f))), 1.0f);
    const float energy = p.y;
    const float tilt   = __fmaf_rn(p.z, 2.0f, -1.0f);
    const float bw     = __fadd_rn(0.05f, __fmul_rn(p.w, 0.95f));
    int delay = (int)__fmul_rn(64.0f, __fadd_rn(0.5f, __fmul_rn(0.5f, bw)));
    delay = min(max(delay, 1), 480);    // effectively [33, 63]

    // a2 = -log2(e)/att ; exp(-k/att) == ex2(k*a2)
    float inv_att;
    asm("rcp.approx.f32 %0, %1;" : "=f"(inv_att) : "f"(att));
    const float a2 = -LOG2E * inv_att;

    const int i0   = l << 2;
    const int base = row * 64 + i0;     // < 4.1M, fits int
    const float4 n = *reinterpret_cast<const float4*>(noise + base);

    // Envelope recurrence: env(i0+k) = e0 * r^k, energy folded into e0.
    float r, e0, etap;
    asm("ex2.approx.f32 %0, %1;" : "=f"(r)    : "f"(a2));
    asm("ex2.approx.f32 %0, %1;" : "=f"(e0)   : "f"((float)i0 * a2));
    asm("ex2.approx.f32 %0, %1;" : "=f"(etap) : "f"(-(float)delay * a2));
    e0 *= energy;
    const float e1 = e0 * r;
    const float e2 = e1 * r;
    const float e3 = e2 * r;
    const float tf = tilt * etap;       // tilt * exp(delay/att), <= e^7.9, no overflow

    // Tap reloads: elements (i0+k-delay) in [0,30] when valid -> L1 hits.
    const int    j  = i0 - delay;
    const float* np = noise + (base - delay);
    const float m0 = (j + 0 >= 0) ? np[0] : 0.0f;
    const float m1 = (j + 1 >= 0) ? np[1] : 0.0f;
    const float m2 = (j + 2 >= 0) ? np[2] : 0.0f;
    const float m3 = (j + 3 >= 0) ? np[3] : 0.0f;

    const float y0 = e0 * __fmaf_rn(tf, m0, n.x);
    const float y1 = e1 * __fmaf_rn(tf, m1, n.y);
    const float y2 = e2 * __fmaf_rn(tf, m2, n.z);
    const float y3 = e3 * __fmaf_rn(tf, m3, n.w);

    // Sum of squares across this row's 16 lanes: 4-step butterfly.
    float ss = y0 * y0 + y1 * y1 + y2 * y2 + y3 * y3;
    ss += __shfl_xor_sync(0xFFFFFFFFu, ss, 8);
    ss += __shfl_xor_sync(0xFFFFFFFFu, ss, 4);
    ss += __shfl_xor_sync(0xFFFFFFFFu, ss, 2);
    ss += __shfl_xor_sync(0xFFFFFFFFu, ss, 1);

    const float inv_rms = rsqrtf(ss * (1.0f / 64.0f) + 1e-5f);

    float4 o;
    o.x = y0 * inv_rms;
    o.y = y1 * inv_rms;
    o.z = y2 * inv_rms;
    o.w = y3 * inv_rms;
    *reinterpret_cast<float4*>(out + base) = o;
}

extern "C" void kernel_launch(void* const* d_in, const int* in_sizes, int n_in,
                              void* d_out, int out_size)
{
    const float4* params = (const float4*)d_in[0];  // [32,2000,4]
    const float*  noise  = (const float*)d_in[1];   // [32,2000,64]
    float* out = (float*)d_out;                     // [32, 2000*64]

    // Exact: 64000 rows * 16 lanes / 256 threads = 4000 blocks.
    tcn_kernel<<<(N_ROWS * 16) / 256, 256>>>(params, noise, out);
}